// round 2
// baseline (speedup 1.0000x reference)
#include <cuda_runtime.h>
#include <cuda_bf16.h>

// out[i] = -0.5*(df + D) * log(1 + sum_j (X[i,j]-mean[j])^2 / df)
// X: [N, D] fp32, mean: [D] fp32, df: [1] fp32, out: [N] fp32
//
// Layout: one WARP per row (no block barriers in hot path).
// mean staged into shared memory once per CTA (removes per-row L2 traffic).
// X read with __ldcs (streaming, evict-first: zero reuse).

#define SMEM_MEAN4 1024   // float4 slots for mean in smem (covers D <= 4096)
#define WARPS_PER_CTA 8

__global__ __launch_bounds__(256)
void row_logden_warp_kernel(const float4* __restrict__ X,
                            const float4* __restrict__ mean4,
                            const float* __restrict__ df,
                            float* __restrict__ out,
                            int nrows, int ncols4, int d_full)
{
    __shared__ float4 smean[SMEM_MEAN4];

    // Stage mean into smem (cooperative, once per CTA).
    const int smem_n = (ncols4 < SMEM_MEAN4) ? ncols4 : SMEM_MEAN4;
    for (int i = threadIdx.x; i < smem_n; i += blockDim.x)
        smean[i] = mean4[i];
    __syncthreads();

    const int lane = threadIdx.x & 31;
    const int warp = threadIdx.x >> 5;
    const int row  = blockIdx.x * WARPS_PER_CTA + warp;
    if (row >= nrows) return;

    const float4* __restrict__ xr = X + (size_t)row * ncols4;

    float acc = 0.0f;
    int i = lane;

    // Main loop: 4 independent streaming loads per lane per iteration.
    // For D=4096 (ncols4=1024): 8 iterations of 4 x float4 per lane.
    #pragma unroll 2
    for (; i + 96 < ncols4; i += 128) {
        float4 x0 = __ldcs(xr + i);
        float4 x1 = __ldcs(xr + i + 32);
        float4 x2 = __ldcs(xr + i + 64);
        float4 x3 = __ldcs(xr + i + 96);
        float4 m0 = smean[i];
        float4 m1 = smean[i + 32];
        float4 m2 = smean[i + 64];
        float4 m3 = smean[i + 96];

        float a;
        a = x0.x - m0.x; acc = fmaf(a, a, acc);
        a = x0.y - m0.y; acc = fmaf(a, a, acc);
        a = x0.z - m0.z; acc = fmaf(a, a, acc);
        a = x0.w - m0.w; acc = fmaf(a, a, acc);
        a = x1.x - m1.x; acc = fmaf(a, a, acc);
        a = x1.y - m1.y; acc = fmaf(a, a, acc);
        a = x1.z - m1.z; acc = fmaf(a, a, acc);
        a = x1.w - m1.w; acc = fmaf(a, a, acc);
        a = x2.x - m2.x; acc = fmaf(a, a, acc);
        a = x2.y - m2.y; acc = fmaf(a, a, acc);
        a = x2.z - m2.z; acc = fmaf(a, a, acc);
        a = x2.w - m2.w; acc = fmaf(a, a, acc);
        a = x3.x - m3.x; acc = fmaf(a, a, acc);
        a = x3.y - m3.y; acc = fmaf(a, a, acc);
        a = x3.z - m3.z; acc = fmaf(a, a, acc);
        a = x3.w - m3.w; acc = fmaf(a, a, acc);
    }
    // Tail: one float4 per lane per step; mean from smem if staged, else global.
    for (; i < ncols4; i += 32) {
        float4 x = __ldcs(xr + i);
        float4 m = (i < smem_n) ? smean[i] : mean4[i];
        float a;
        a = x.x - m.x; acc = fmaf(a, a, acc);
        a = x.y - m.y; acc = fmaf(a, a, acc);
        a = x.z - m.z; acc = fmaf(a, a, acc);
        a = x.w - m.w; acc = fmaf(a, a, acc);
    }

    // Warp-only reduction (no block barriers).
    #pragma unroll
    for (int off = 16; off > 0; off >>= 1)
        acc += __shfl_xor_sync(0xFFFFFFFFu, acc, off);

    if (lane == 0) {
        const float dfv = __ldg(df);
        const float logden = log1pf(acc / dfv);
        out[row] = -0.5f * (dfv + (float)d_full) * logden;
    }
}

extern "C" void kernel_launch(void* const* d_in, const int* in_sizes, int n_in,
                              void* d_out, int out_size)
{
    const float* X    = (const float*)d_in[0];
    const float* mean = (const float*)d_in[1];
    const float* df   = (const float*)d_in[2];
    float* out        = (float*)d_out;

    const int D = in_sizes[1];          // 4096
    const int N = in_sizes[0] / D;      // 8192
    const int ncols4 = D / 4;           // 1024

    const int grid = (N + WARPS_PER_CTA - 1) / WARPS_PER_CTA;
    row_logden_warp_kernel<<<grid, 256>>>((const float4*)X, (const float4*)mean,
                                          df, out, N, ncols4, D);
}

// round 3
// speedup vs baseline: 1.1097x; 1.1097x over previous
#include <cuda_runtime.h>
#include <cuda_bf16.h>

// out[i] = -0.5*(df + D) * log(1 + sum_j (X[i,j]-mean[j])^2 / df)
// X: [N, D] fp32, mean: [D] fp32, df: [1] fp32, out: [N] fp32
//
// Fast path (D == 4096): persistent block-per-row, mean held in registers,
// software-pipelined loads (next row's X issued before current row's reduce).

#define TPB 256

__global__ __launch_bounds__(TPB, 5)
void row_logden_reg_kernel(const float4* __restrict__ X,
                           const float4* __restrict__ mean4,
                           const float* __restrict__ df,
                           float* __restrict__ out,
                           int nrows)
{
    const int t    = threadIdx.x;
    const int lane = t & 31;
    const int wid  = t >> 5;

    // mean columns owned by this thread, loaded ONCE (persistent CTA).
    const float4 m0 = mean4[t];
    const float4 m1 = mean4[t + 256];
    const float4 m2 = mean4[t + 512];
    const float4 m3 = mean4[t + 768];

    const float dfv   = df[0];
    const float scale = -0.5f * (dfv + 4096.0f);

    __shared__ float wsum[8];

    int row = blockIdx.x;
    if (row >= nrows) return;

    // Prologue: load first row (4 independent LDG.128, streaming).
    const float4* xr = X + (size_t)row * 1024;
    float4 x0 = __ldcs(xr + t);
    float4 x1 = __ldcs(xr + t + 256);
    float4 x2 = __ldcs(xr + t + 512);
    float4 x3 = __ldcs(xr + t + 768);

    while (true) {
        // Consume current row's x regs into 4 independent accumulators.
        float a0 = 0.f, a1 = 0.f, a2 = 0.f, a3 = 0.f;
        float d;
        d = x0.x - m0.x; a0 = fmaf(d, d, a0);
        d = x0.y - m0.y; a1 = fmaf(d, d, a1);
        d = x0.z - m0.z; a2 = fmaf(d, d, a2);
        d = x0.w - m0.w; a3 = fmaf(d, d, a3);
        d = x1.x - m1.x; a0 = fmaf(d, d, a0);
        d = x1.y - m1.y; a1 = fmaf(d, d, a1);
        d = x1.z - m1.z; a2 = fmaf(d, d, a2);
        d = x1.w - m1.w; a3 = fmaf(d, d, a3);
        d = x2.x - m2.x; a0 = fmaf(d, d, a0);
        d = x2.y - m2.y; a1 = fmaf(d, d, a1);
        d = x2.z - m2.z; a2 = fmaf(d, d, a2);
        d = x2.w - m2.w; a3 = fmaf(d, d, a3);
        d = x3.x - m3.x; a0 = fmaf(d, d, a0);
        d = x3.y - m3.y; a1 = fmaf(d, d, a1);
        d = x3.z - m3.z; a2 = fmaf(d, d, a2);
        d = x3.w - m3.w; a3 = fmaf(d, d, a3);
        float acc = (a0 + a1) + (a2 + a3);

        // Prefetch NEXT row before the reduction: loads fly during barriers.
        const int next = row + gridDim.x;
        if (next < nrows) {
            const float4* xn = X + (size_t)next * 1024;
            x0 = __ldcs(xn + t);
            x1 = __ldcs(xn + t + 256);
            x2 = __ldcs(xn + t + 512);
            x3 = __ldcs(xn + t + 768);
        }

        // Reduce current row.
        #pragma unroll
        for (int off = 16; off > 0; off >>= 1)
            acc += __shfl_xor_sync(0xFFFFFFFFu, acc, off);
        if (lane == 0) wsum[wid] = acc;
        __syncthreads();
        if (wid == 0) {
            float s = wsum[lane & 7];
            s += __shfl_xor_sync(0xFFFFFFFFu, s, 4);
            s += __shfl_xor_sync(0xFFFFFFFFu, s, 2);
            s += __shfl_xor_sync(0xFFFFFFFFu, s, 1);
            if (lane == 0) out[row] = scale * log1pf(s / dfv);
        }
        __syncthreads();   // protect wsum before next row reuses it

        if (next >= nrows) break;
        row = next;
    }
}

// Generic fallback (any D multiple of 4): block-per-row, R1 style.
__global__ __launch_bounds__(256)
void row_logden_generic_kernel(const float4* __restrict__ X,
                               const float4* __restrict__ mean,
                               const float* __restrict__ df,
                               float* __restrict__ out,
                               int ncols4, int d_full)
{
    const int row = blockIdx.x;
    const float4* xr = X + (size_t)row * ncols4;

    float acc = 0.0f;
    for (int i = threadIdx.x; i < ncols4; i += blockDim.x) {
        float4 x = xr[i];
        float4 m = mean[i];
        float a;
        a = x.x - m.x; acc = fmaf(a, a, acc);
        a = x.y - m.y; acc = fmaf(a, a, acc);
        a = x.z - m.z; acc = fmaf(a, a, acc);
        a = x.w - m.w; acc = fmaf(a, a, acc);
    }

    #pragma unroll
    for (int off = 16; off > 0; off >>= 1)
        acc += __shfl_xor_sync(0xFFFFFFFFu, acc, off);

    __shared__ float warp_sums[8];
    const int lane = threadIdx.x & 31;
    const int wid = threadIdx.x >> 5;
    if (lane == 0) warp_sums[wid] = acc;
    __syncthreads();

    if (wid == 0) {
        float s = (lane < (blockDim.x >> 5)) ? warp_sums[lane] : 0.0f;
        #pragma unroll
        for (int off = 4; off > 0; off >>= 1)
            s += __shfl_xor_sync(0xFFFFFFFFu, s, off);
        if (lane == 0) {
            const float dfv = df[0];
            out[row] = -0.5f * (dfv + (float)d_full) * log1pf(s / dfv);
        }
    }
}

extern "C" void kernel_launch(void* const* d_in, const int* in_sizes, int n_in,
                              void* d_out, int out_size)
{
    const float* X    = (const float*)d_in[0];
    const float* mean = (const float*)d_in[1];
    const float* df   = (const float*)d_in[2];
    float* out        = (float*)d_out;

    const int D = in_sizes[1];
    const int N = in_sizes[0] / D;
    const int ncols4 = D / 4;

    if (D == 4096) {
        const int grid = 592;   // 148 SMs x 4 CTAs: one persistent wave
        row_logden_reg_kernel<<<grid, TPB>>>((const float4*)X,
                                             (const float4*)mean, df, out, N);
    } else {
        row_logden_generic_kernel<<<N, 256>>>((const float4*)X,
                                              (const float4*)mean, df, out,
                                              ncols4, D);
    }
}